// round 1
// baseline (speedup 1.0000x reference)
#include <cuda_runtime.h>
#include <math.h>

// Problem shape (fixed by the dataset): B=16, N=131072, C=2.
#define B_MAX 16
#define N_FIX 131072
#define K1_THREADS 128
#define K1_ITERS 16

// Per-batch accumulators: [0:21) Hpp sym(p<=q), [21:27) g_p,
// [27:48) term sym(p<=q), [48:54) g_eff correction.
__device__ float g_acc[B_MAX * 54];
__device__ float g_pose_raw[B_MAX * 6];
// Per-node intermediates: Hpd[6], inv_H_dd, g_d  (8 floats/node)
__device__ float g_interm[(size_t)B_MAX * N_FIX * 8];

__global__ void zero_acc_kernel(int n) {
    int i = blockIdx.x * blockDim.x + threadIdx.x;
    if (i < n) g_acc[i] = 0.0f;
}

__global__ __launch_bounds__(K1_THREADS) void k1_kernel(
    const float* __restrict__ r, const float* __restrict__ w,
    const float* __restrict__ Jp, const float* __restrict__ Jd,
    const float* __restrict__ lmbda, int N)
{
    const int b = blockIdx.y;
    float lam = lmbda[b];
    lam = isnan(lam) ? 100.0f : lam;
    lam = fmaxf(lam, 0.001f);

    float acc[54];
#pragma unroll
    for (int k = 0; k < 54; k++) acc[k] = 0.0f;

    const size_t base = (size_t)b * (size_t)N;
    const int n0 = blockIdx.x * (K1_THREADS * K1_ITERS) + threadIdx.x;

#pragma unroll
    for (int it = 0; it < K1_ITERS; it++) {
        int n = n0 + it * K1_THREADS;
        if (n < N) {
            size_t idx = base + (size_t)n;
            const float4* jp4 = (const float4*)(Jp + idx * 12);
            float4 a0 = jp4[0];
            float4 a1 = jp4[1];
            float4 a2 = jp4[2];
            float jp[12] = {a0.x,a0.y,a0.z,a0.w, a1.x,a1.y,a1.z,a1.w,
                            a2.x,a2.y,a2.z,a2.w};
            float2 rv = ((const float2*)r)[idx];
            float2 wv = ((const float2*)w)[idx];
            float2 jd = ((const float2*)Jd)[idx];
            float conf = wv.x;

            float s0[6], s1[6];
#pragma unroll
            for (int p = 0; p < 6; p++) { s0[p] = conf * jp[p]; s1[p] = conf * jp[6+p]; }

            // H_pp (symmetric upper)
            int t = 0;
#pragma unroll
            for (int p = 0; p < 6; p++)
#pragma unroll
                for (int q = p; q < 6; q++) { acc[t] += s0[p]*jp[q] + s1[p]*jp[6+q]; t++; }

            // g_p
#pragma unroll
            for (int p = 0; p < 6; p++) acc[21+p] += s0[p]*rv.x + s1[p]*rv.y;

            // Per-node pieces
            float hpd[6];
#pragma unroll
            for (int p = 0; p < 6; p++) hpd[p] = s0[p]*jd.x + s1[p]*jd.y;
            float hdd = conf * (jd.x*jd.x + jd.y*jd.y);
            float gd  = conf * (jd.x*rv.x + jd.y*rv.y);
            float invh = 1.0f / fmaxf(hdd + lam + wv.y + 1e-4f, 1e-4f);

            // term_to_sub (symmetric upper) + g_eff correction
            float tc[6];
#pragma unroll
            for (int p = 0; p < 6; p++) tc[p] = invh * hpd[p];
            t = 27;
#pragma unroll
            for (int p = 0; p < 6; p++)
#pragma unroll
                for (int q = p; q < 6; q++) { acc[t] += tc[p]*hpd[q]; t++; }
#pragma unroll
            for (int p = 0; p < 6; p++) acc[48+p] += tc[p]*gd;

            // Stash per-node intermediates for the depth pass
            float4* o4 = (float4*)(g_interm + idx * 8);
            o4[0] = make_float4(hpd[0], hpd[1], hpd[2], hpd[3]);
            o4[1] = make_float4(hpd[4], hpd[5], invh, gd);
        }
    }

    // Block reduction: warp shuffle -> shared atomics -> global atomics
    __shared__ float s_acc[54];
    if (threadIdx.x < 54) s_acc[threadIdx.x] = 0.0f;
    __syncthreads();
    const int lane = threadIdx.x & 31;
#pragma unroll
    for (int k = 0; k < 54; k++) {
        float v = acc[k];
#pragma unroll
        for (int off = 16; off > 0; off >>= 1)
            v += __shfl_down_sync(0xffffffffu, v, off);
        if (lane == 0) atomicAdd(&s_acc[k], v);
    }
    __syncthreads();
    if (threadIdx.x < 54)
        atomicAdd(&g_acc[b * 54 + threadIdx.x], s_acc[threadIdx.x]);
}

// One warp; thread b solves batch b's 6x6 SPD system (no pivoting needed:
// H_eff = SchurPSD + (lam+1)I then *1.01 on diag -> lambda_min >= ~1).
__global__ void k2_kernel(float* __restrict__ out_pose,
                          const float* __restrict__ lmbda,
                          const int* __restrict__ iter_idx, int B)
{
    int b = threadIdx.x;
    bool active = (b < B);
    float x[6] = {0.f,0.f,0.f,0.f,0.f,0.f};
    bool nanflag = false;

    if (active) {
        const float* a = g_acc + b * 54;
        float lam = lmbda[b];
        lam = isnan(lam) ? 100.0f : lam;
        lam = fmaxf(lam, 0.001f);

        float H[6][6], g[6];
        int t = 0;
#pragma unroll
        for (int p = 0; p < 6; p++)
#pragma unroll
            for (int q = p; q < 6; q++) {
                float v = a[t] - a[27 + t];
                H[p][q] = v; H[q][p] = v; t++;
            }
#pragma unroll
        for (int p = 0; p < 6; p++) g[p] = a[21+p] - a[48+p];
#pragma unroll
        for (int p = 0; p < 6; p++) H[p][p] += lam;

        int ii = iter_idx ? *iter_idx : 1;
        if (ii >= 2) {
#pragma unroll
            for (int p = 3; p < 6; p++) g[p] = 0.0f;
#pragma unroll
            for (int p = 3; p < 6; p++)
#pragma unroll
                for (int q = 3; q < 6; q++) H[p][q] += 100000000.0f;
        }
#pragma unroll
        for (int p = 0; p < 6; p++) H[p][p] += 1.0f;
#pragma unroll
        for (int p = 0; p < 6; p++) H[p][p] += 0.01f * H[p][p];

        // Unrolled Gaussian elimination (registers only)
#pragma unroll
        for (int k = 0; k < 6; k++) {
            float inv = 1.0f / H[k][k];
#pragma unroll
            for (int i2 = k+1; i2 < 6; i2++) {
                float f = H[i2][k] * inv;
#pragma unroll
                for (int j = k; j < 6; j++) H[i2][j] -= f * H[k][j];
                g[i2] -= f * g[k];
            }
        }
#pragma unroll
        for (int k = 5; k >= 0; k--) {
            float s = g[k];
#pragma unroll
            for (int j = k+1; j < 6; j++) s -= H[k][j] * x[j];
            x[k] = s / H[k][k];
        }
#pragma unroll
        for (int p = 0; p < 6; p++) nanflag = nanflag || isnan(x[p]);
    }

    // jnp.any over the WHOLE (B,6) array -> cross-batch any
    unsigned ball = __ballot_sync(0xffffffffu, nanflag);
    bool anynan = (ball != 0u);

    if (active) {
#pragma unroll
        for (int p = 0; p < 6; p++) {
            g_pose_raw[b*6 + p] = x[p];  // raw (pre-clip) pose feeds depth pass
            out_pose[b*6 + p] = anynan ? 0.0f
                                       : fminf(fmaxf(x[p], -2.0f), 2.0f);
        }
    }
}

__global__ void k3_kernel(float* __restrict__ out_depth, int N, int total)
{
    int i = blockIdx.x * blockDim.x + threadIdx.x;
    if (i >= total) return;
    int b = i / N;
    const float4 v0 = ((const float4*)g_interm)[2*(size_t)i];
    const float4 v1 = ((const float4*)g_interm)[2*(size_t)i + 1];
    const float* pb = g_pose_raw + b*6;
    float v = v0.x*pb[0] + v0.y*pb[1] + v0.z*pb[2] + v0.w*pb[3]
            + v1.x*pb[4] + v1.y*pb[5];
    float d = v1.z * (v1.w - v);
    out_depth[i] = fminf(fmaxf(d, -5.0f), 5.0f);
}

extern "C" void kernel_launch(void* const* d_in, const int* in_sizes, int n_in,
                              void* d_out, int out_size)
{
    const float* r     = (const float*)d_in[0];
    const float* w     = (const float*)d_in[1];
    const float* Jp    = (const float*)d_in[2];
    const float* Jd    = (const float*)d_in[3];
    const float* lmbda = (const float*)d_in[4];
    const int* iter_idx = (n_in > 5) ? (const int*)d_in[5] : nullptr;

    int B = in_sizes[4];                       // lmbda has B elements
    long long total = (long long)in_sizes[0] / 2;  // B*N (C=2)
    int N = (int)(total / B);
    float* out = (float*)d_out;

    zero_acc_kernel<<<1, 1024>>>(B * 54);

    dim3 g1((N + K1_THREADS*K1_ITERS - 1) / (K1_THREADS*K1_ITERS), B);
    k1_kernel<<<g1, K1_THREADS>>>(r, w, Jp, Jd, lmbda, N);

    k2_kernel<<<1, 32>>>(out, lmbda, iter_idx, B);

    int blocks3 = (int)((total + 255) / 256);
    k3_kernel<<<blocks3, 256>>>(out + (size_t)B * 6, N, (int)total);
}

// round 2
// speedup vs baseline: 1.1870x; 1.1870x over previous
#include <cuda_runtime.h>
#include <math.h>

// Problem shape (fixed by the dataset): B=16, N=131072, C=2.
#define B_MAX 16
#define N_FIX 131072
#define K1_THREADS 128
#define K1_ITERS 16

// Per-batch accumulators (27): [0:21) (Hpp - term) sym(p<=q), [21:27) (g_p - corr).
// Zero-initialized at module load; k2 re-zeroes after consuming -> invariant
// holds across graph replays.
__device__ float g_acc[B_MAX * 27];
__device__ float g_pose_raw[B_MAX * 6];
// Per-node intermediates: Hpd[6], inv_H_dd, g_d  (8 floats/node)
__device__ float g_interm[(size_t)B_MAX * N_FIX * 8];

__global__ __launch_bounds__(K1_THREADS) void k1_kernel(
    const float* __restrict__ r, const float* __restrict__ w,
    const float* __restrict__ Jp, const float* __restrict__ Jd,
    const float* __restrict__ lmbda, int N)
{
    const int b = blockIdx.y;
    float lam = lmbda[b];
    lam = isnan(lam) ? 100.0f : lam;
    lam = fmaxf(lam, 0.001f);

    float acc[27];
#pragma unroll
    for (int k = 0; k < 27; k++) acc[k] = 0.0f;

    const size_t base = (size_t)b * (size_t)N;
    const int n0 = blockIdx.x * (K1_THREADS * K1_ITERS) + threadIdx.x;

#pragma unroll 4
    for (int it = 0; it < K1_ITERS; it++) {
        int n = n0 + it * K1_THREADS;
        if (n < N) {
            size_t idx = base + (size_t)n;
            // Streaming loads (evict-first in L2) so g_interm stays resident.
            const float4* jp4 = (const float4*)(Jp + idx * 12);
            float4 a0 = __ldcs(jp4 + 0);
            float4 a1 = __ldcs(jp4 + 1);
            float4 a2 = __ldcs(jp4 + 2);
            float jp[12] = {a0.x,a0.y,a0.z,a0.w, a1.x,a1.y,a1.z,a1.w,
                            a2.x,a2.y,a2.z,a2.w};
            float2 rv = __ldcs((const float2*)r + idx);
            float2 wv = __ldcs((const float2*)w + idx);
            float2 jd = __ldcs((const float2*)Jd + idx);
            float conf = wv.x;

            float s0[6], s1[6];
#pragma unroll
            for (int p = 0; p < 6; p++) { s0[p] = conf * jp[p]; s1[p] = conf * jp[6+p]; }

            // Per-node Schur pieces
            float hpd[6];
#pragma unroll
            for (int p = 0; p < 6; p++) hpd[p] = s0[p]*jd.x + s1[p]*jd.y;
            float hdd = conf * (jd.x*jd.x + jd.y*jd.y);
            float gd  = conf * (jd.x*rv.x + jd.y*rv.y);
            float invh = 1.0f / fmaxf(hdd + lam + wv.y + 1e-4f, 1e-4f);
            float tc[6];
#pragma unroll
            for (int p = 0; p < 6; p++) tc[p] = invh * hpd[p];

            // Fused accumulation: (H_pp - term) and (g_p - correction)
            int t = 0;
#pragma unroll
            for (int p = 0; p < 6; p++)
#pragma unroll
                for (int q = p; q < 6; q++) {
                    acc[t] += s0[p]*jp[q] + s1[p]*jp[6+q] - tc[p]*hpd[q];
                    t++;
                }
#pragma unroll
            for (int p = 0; p < 6; p++)
                acc[21+p] += s0[p]*rv.x + s1[p]*rv.y - tc[p]*gd;

            // Stash per-node intermediates for the depth pass (normal wb ->
            // lands in L2 and, with streamed inputs evict-first, stays there).
            float4* o4 = (float4*)(g_interm + idx * 8);
            o4[0] = make_float4(hpd[0], hpd[1], hpd[2], hpd[3]);
            o4[1] = make_float4(hpd[4], hpd[5], invh, gd);
        }
    }

    // Block reduction: warp shuffle -> shared atomics -> global atomics
    __shared__ float s_acc[27];
    if (threadIdx.x < 27) s_acc[threadIdx.x] = 0.0f;
    __syncthreads();
    const int lane = threadIdx.x & 31;
#pragma unroll
    for (int k = 0; k < 27; k++) {
        float v = acc[k];
#pragma unroll
        for (int off = 16; off > 0; off >>= 1)
            v += __shfl_down_sync(0xffffffffu, v, off);
        if (lane == 0) atomicAdd(&s_acc[k], v);
    }
    __syncthreads();
    if (threadIdx.x < 27)
        atomicAdd(&g_acc[b * 27 + threadIdx.x], s_acc[threadIdx.x]);
}

// One warp; thread b solves batch b's 6x6 SPD system (no pivoting needed:
// H_eff = SchurPSD + (lam+1)I then *1.01 on diag -> lambda_min >= ~1).
// Also re-zeroes g_acc for the next graph replay.
__global__ void k2_kernel(float* __restrict__ out_pose,
                          const float* __restrict__ lmbda,
                          const int* __restrict__ iter_idx, int B)
{
    int b = threadIdx.x;
    bool active = (b < B);
    float x[6] = {0.f,0.f,0.f,0.f,0.f,0.f};
    bool nanflag = false;

    if (active) {
        const float* a = g_acc + b * 27;
        float lam = lmbda[b];
        lam = isnan(lam) ? 100.0f : lam;
        lam = fmaxf(lam, 0.001f);

        float H[6][6], g[6];
        int t = 0;
#pragma unroll
        for (int p = 0; p < 6; p++)
#pragma unroll
            for (int q = p; q < 6; q++) {
                float v = a[t];
                H[p][q] = v; H[q][p] = v; t++;
            }
#pragma unroll
        for (int p = 0; p < 6; p++) g[p] = a[21+p];
#pragma unroll
        for (int p = 0; p < 6; p++) H[p][p] += lam;

        int ii = iter_idx ? *iter_idx : 1;
        if (ii >= 2) {
#pragma unroll
            for (int p = 3; p < 6; p++) g[p] = 0.0f;
#pragma unroll
            for (int p = 3; p < 6; p++)
#pragma unroll
                for (int q = 3; q < 6; q++) H[p][q] += 100000000.0f;
        }
#pragma unroll
        for (int p = 0; p < 6; p++) H[p][p] += 1.0f;
#pragma unroll
        for (int p = 0; p < 6; p++) H[p][p] += 0.01f * H[p][p];

        // Unrolled Gaussian elimination (registers only)
#pragma unroll
        for (int k = 0; k < 6; k++) {
            float inv = 1.0f / H[k][k];
#pragma unroll
            for (int i2 = k+1; i2 < 6; i2++) {
                float f = H[i2][k] * inv;
#pragma unroll
                for (int j = k; j < 6; j++) H[i2][j] -= f * H[k][j];
                g[i2] -= f * g[k];
            }
        }
#pragma unroll
        for (int k = 5; k >= 0; k--) {
            float s = g[k];
#pragma unroll
            for (int j = k+1; j < 6; j++) s -= H[k][j] * x[j];
            x[k] = s / H[k][k];
        }
#pragma unroll
        for (int p = 0; p < 6; p++) nanflag = nanflag || isnan(x[p]);
    }

    // jnp.any over the WHOLE (B,6) array -> cross-batch any
    unsigned ball = __ballot_sync(0xffffffffu, nanflag);
    bool anynan = (ball != 0u);

    if (active) {
#pragma unroll
        for (int p = 0; p < 6; p++) {
            g_pose_raw[b*6 + p] = x[p];  // raw (pre-clip) pose feeds depth pass
            out_pose[b*6 + p] = anynan ? 0.0f
                                       : fminf(fmaxf(x[p], -2.0f), 2.0f);
        }
    }

    // All reads of g_acc above are done (single warp, syncthreads for safety);
    // re-zero for the next replay of the captured graph.
    __syncthreads();
    for (int i = threadIdx.x; i < B * 27; i += blockDim.x) g_acc[i] = 0.0f;
}

__global__ void k3_kernel(float* __restrict__ out_depth, int N)
{
    const int b = blockIdx.y;
    int n = blockIdx.x * blockDim.x + threadIdx.x;
    if (n >= N) return;
    size_t i = (size_t)b * (size_t)N + (size_t)n;
    // These should mostly hit L2 (written by k1, inputs streamed evict-first).
    const float4 v0 = __ldcs((const float4*)g_interm + 2*i);
    const float4 v1 = __ldcs((const float4*)g_interm + 2*i + 1);
    const float* pb = g_pose_raw + b*6;
    float v = v0.x*pb[0] + v0.y*pb[1] + v0.z*pb[2] + v0.w*pb[3]
            + v1.x*pb[4] + v1.y*pb[5];
    float d = v1.z * (v1.w - v);
    __stcs(out_depth + i, fminf(fmaxf(d, -5.0f), 5.0f));
}

extern "C" void kernel_launch(void* const* d_in, const int* in_sizes, int n_in,
                              void* d_out, int out_size)
{
    const float* r     = (const float*)d_in[0];
    const float* w     = (const float*)d_in[1];
    const float* Jp    = (const float*)d_in[2];
    const float* Jd    = (const float*)d_in[3];
    const float* lmbda = (const float*)d_in[4];
    const int* iter_idx = (n_in > 5) ? (const int*)d_in[5] : nullptr;

    int B = in_sizes[4];                       // lmbda has B elements
    long long total = (long long)in_sizes[0] / 2;  // B*N (C=2)
    int N = (int)(total / B);
    float* out = (float*)d_out;

    dim3 g1((N + K1_THREADS*K1_ITERS - 1) / (K1_THREADS*K1_ITERS), B);
    k1_kernel<<<g1, K1_THREADS>>>(r, w, Jp, Jd, lmbda, N);

    k2_kernel<<<1, 32>>>(out, lmbda, iter_idx, B);

    dim3 g3((N + 255) / 256, B);
    k3_kernel<<<g3, 256>>>(out + (size_t)B * 6, N);
}